// round 14
// baseline (speedup 1.0000x reference)
#include <cuda_runtime.h>
#include <cuda_fp16.h>
#include <stdint.h>

// ============================================================================
// ExpertLinear as ONE GEMM: C(4096x1024) = A(4096x8320) * W'(1024x8320)^T
//   A[b, e*1024+i] = blend[b,e]*x[b,i];  A[b,8192+e] = blend[b,e]; pad 0
//   W'[o, e*1024+i] = weight[e,o,i];     W'[o,8192+e] = bias[e,o]; pad 0
// tcgen05 fp16 SS GEMM (fp32 accum), rel_err ~4e-4 (threshold 1e-3).
// Round 14: the GEMM was LTS-bound on B (545MB of L2 reads: 32 CTAs per
// tileX each re-reading the same W rows). Fix by geometry: TM=256 x TN=128
// per CTA (still 128 CTAs = 1 wave): B tile halves to 128 rows/16KB and two
// M=128 MMA groups (TMEM cols [0,128) and [128,256)) share ONE B descriptor.
// B traffic 545->272MB; GEMM flips tensor-bound (~47us floor).
// A (256 rows) built in-kernel from x_fp16 * blend (fp16x2), 8 rows/thread.
// KC=64 (130 chunks), 3-stage, commit-mbar gated refill (proven schedule).
// ============================================================================

#if defined(__CUDA_ARCH_FEAT_SM103_ALL) || defined(__CUDA_ARCH_FEAT_SM100_ALL)
#define HAS_TC 1
#else
#define HAS_TC 0
#endif

#define B_TOT   4096
#define IN_DIM  1024
#define OUT_DIM 1024
#define NEXP    8
#define KTOT    8320                   // 130*64 (8192 data + 8 bias + pad)

#define KC_TC   64
#define NCH_TC  (KTOT / KC_TC)         // 130
#define TM_TC   256
#define TN_TC   128
#define A_TILE_TC (TM_TC * 128)        // 32768 (256 rows x 128B)
#define B_TILE_TC (TN_TC * 128)        // 16384 (128 rows x 128B)
#define STAGE_TC  (A_TILE_TC + B_TILE_TC)  // 49152
#define CTRL_TC   16384                    // tmem ptr, mbars, 8KB blend slab
#define SMEM_TC   (CTRL_TC + 3 * STAGE_TC) // 163840

// Global scratch (allocation-free rule: __device__ globals)
__device__ __align__(16) __half g_Wh[(size_t)OUT_DIM * KTOT];   // 17.0 MB
__device__ __align__(16) __half g_xh[(size_t)B_TOT * IN_DIM];   // 8.4 MB

// ---------------------------------------------------------------------------
__device__ __forceinline__ uint32_t smem_u32(const void* p) {
    uint32_t a;
    asm("{ .reg .u64 t; cvta.to.shared.u64 t, %1; cvt.u32.u64 %0, t; }"
        : "=r"(a) : "l"(p));
    return a;
}

__device__ __forceinline__ void cp_async16(uint32_t saddr, const void* gptr) {
    asm volatile("cp.async.cg.shared.global [%0], [%1], 16;"
                 :: "r"(saddr), "l"(gptr) : "memory");
}

__device__ __forceinline__ uint32_t pack_h2(float a, float b) {
    uint32_t r;
    asm("cvt.rn.f16x2.f32 %0, %1, %2;" : "=r"(r) : "f"(b), "f"(a));
    return r;
}

__device__ __forceinline__ uint32_t hmul2(uint32_t a, uint32_t b) {
    uint32_t r;
    asm("mul.f16x2 %0, %1, %2;" : "=r"(r) : "r"(a), "r"(b));
    return r;
}

__device__ __forceinline__ void mbar_wait(uint32_t mbar, uint32_t parity) {
    asm volatile(
        "{\n\t.reg .pred P;\n\t"
        "WL_%=:\n\t"
        "mbarrier.try_wait.parity.acquire.cta.shared::cta.b64 P, [%0], %1, 0x989680;\n\t"
        "@P bra.uni WD_%=;\n\t"
        "bra.uni WL_%=;\n\t"
        "WD_%=:\n\t}"
        :: "r"(mbar), "r"(parity) : "memory");
}

__device__ __forceinline__ void sts128(uint32_t addr, uint32_t a, uint32_t b,
                                       uint32_t c, uint32_t d) {
    asm volatile("st.shared.v4.b32 [%0], {%1,%2,%3,%4};"
                 :: "r"(addr), "r"(a), "r"(b), "r"(c), "r"(d) : "memory");
}

// ---------------------------------------------------------------------------
// Kernel 1: W' (+bias columns, +zero pad) -> fp16 scratch (8-wide)
// ---------------------------------------------------------------------------
__global__ void __launch_bounds__(256)
convert_w_kernel(const float* __restrict__ weight, const float* __restrict__ bias) {
    int o = blockIdx.y;
    int kk = (blockIdx.x * 256 + threadIdx.x) * 8;
    if (kk >= KTOT) return;
    float v[8];
    if (kk < NEXP * IN_DIM) {
        int e = kk >> 10, i = kk & 1023;
        const float4* src = reinterpret_cast<const float4*>(
            weight + (size_t)e * OUT_DIM * IN_DIM + (size_t)o * IN_DIM + i);
        float4 w0 = src[0], w1 = src[1];
        v[0] = w0.x; v[1] = w0.y; v[2] = w0.z; v[3] = w0.w;
        v[4] = w1.x; v[5] = w1.y; v[6] = w1.z; v[7] = w1.w;
    } else {
        #pragma unroll
        for (int j = 0; j < 8; ++j) {
            int e = kk + j - NEXP * IN_DIM;
            v[j] = (e >= 0 && e < NEXP) ? bias[(size_t)e * OUT_DIM + o] : 0.0f;
        }
    }
    uint4 h = make_uint4(pack_h2(v[0], v[1]), pack_h2(v[2], v[3]),
                         pack_h2(v[4], v[5]), pack_h2(v[6], v[7]));
    *reinterpret_cast<uint4*>(&g_Wh[(size_t)o * KTOT + kk]) = h;
}

// ---------------------------------------------------------------------------
// Kernel 2: x -> fp16 scratch. One block = 2 rows (256 thr, 8 elems each).
// ---------------------------------------------------------------------------
__global__ void __launch_bounds__(256)
convert_x_kernel(const float* __restrict__ x) {
    int b = blockIdx.x * 2 + (threadIdx.x >> 7);
    int i = (threadIdx.x & 127) * 8;
    const float4* src = reinterpret_cast<const float4*>(x + (size_t)b * IN_DIM + i);
    float4 x0 = src[0], x1 = src[1];
    uint4 h = make_uint4(pack_h2(x0.x, x0.y), pack_h2(x0.z, x0.w),
                         pack_h2(x1.x, x1.y), pack_h2(x1.z, x1.w));
    *reinterpret_cast<uint4*>(&g_xh[(size_t)b * IN_DIM + i]) = h;
}

// ===========================================================================
// tcgen05 path (compiled only when the build has an 'a'-features pass)
// ===========================================================================
#if HAS_TC

__device__ __forceinline__ bool elect1() {
    uint32_t pred;
    asm volatile(
        "{\n\t.reg .pred p;\n\t"
        "elect.sync _|p, 0xFFFFFFFF;\n\t"
        "selp.b32 %0, 1, 0, p;\n\t}"
        : "=r"(pred));
    return pred != 0;
}

// SW128 K-major descriptor: layout=2, version=1 (Blackwell), SBO=64, LBO=1
__device__ __forceinline__ uint64_t smem_desc(uint32_t addr) {
    const uint64_t base = (uint64_t(2) << 61) | (uint64_t(1) << 46) |
                          (uint64_t(64) << 32) | (uint64_t(1) << 16);
    return base | ((uint64_t)(addr >> 4) & 0x3FFF);
}

__device__ __forceinline__ void tc_mma(uint32_t d, uint64_t da, uint64_t db,
                                       uint32_t idesc, uint32_t en) {
    asm volatile(
        "{\n\t.reg .pred p;\n\t"
        "setp.ne.u32 p, %5, 0;\n\t"
        "tcgen05.mma.cta_group::1.kind::f16 [%0], %1, %2, %3, {%4, %4, %4, %4}, p;\n\t}"
        :: "r"(d), "l"(da), "l"(db), "r"(idesc), "r"(0u), "r"(en)
        : "memory");
}

#define TC_LDTM_X32(r, ta)                                                     \
    asm volatile(                                                              \
        "tcgen05.ld.sync.aligned.32x32b.x32.b32 "                              \
        "{%0, %1, %2, %3, %4, %5, %6, %7, "                                    \
        " %8, %9, %10, %11, %12, %13, %14, %15, "                              \
        " %16, %17, %18, %19, %20, %21, %22, %23, "                            \
        " %24, %25, %26, %27, %28, %29, %30, %31}, [%32];"                     \
        : "=r"((r)[0]),  "=r"((r)[1]),  "=r"((r)[2]),  "=r"((r)[3]),           \
          "=r"((r)[4]),  "=r"((r)[5]),  "=r"((r)[6]),  "=r"((r)[7]),           \
          "=r"((r)[8]),  "=r"((r)[9]),  "=r"((r)[10]), "=r"((r)[11]),          \
          "=r"((r)[12]), "=r"((r)[13]), "=r"((r)[14]), "=r"((r)[15]),          \
          "=r"((r)[16]), "=r"((r)[17]), "=r"((r)[18]), "=r"((r)[19]),          \
          "=r"((r)[20]), "=r"((r)[21]), "=r"((r)[22]), "=r"((r)[23]),          \
          "=r"((r)[24]), "=r"((r)[25]), "=r"((r)[26]), "=r"((r)[27]),          \
          "=r"((r)[28]), "=r"((r)[29]), "=r"((r)[30]), "=r"((r)[31])           \
        : "r"(ta))

#endif  // HAS_TC

__global__ void __launch_bounds__(256, 1)
tc_gemm_kernel(const float* __restrict__ blend, float* __restrict__ out) {
#if HAS_TC
    extern __shared__ char smem[];
    const uint32_t sb = smem_u32(smem);
    const int t = threadIdx.x;
    const int wid = t >> 5, lid = t & 31;
    const int tileX = blockIdx.x;   // 0..7  (N tiles of 128)
    const int tileY = blockIdx.y;   // 0..15 (M tiles of 256)

    const uint32_t TMEMP = sb, MB0 = sb + 8, MB1 = sb + 16;
    const uint32_t SBLEND = sb + 64;          // 256 rows x 8 half2(dup) = 8KB
    const uint32_t TILES = sb + CTRL_TC;

    if (t == 0) {
        asm volatile("mbarrier.init.shared.b64 [%0], 1;" :: "r"(MB0) : "memory");
        asm volatile("mbarrier.init.shared.b64 [%0], 1;" :: "r"(MB1) : "memory");
    }
    // blend slab: row r, expert e -> duplicated half2 at SBLEND + r*32 + e*4
    {
        const float4* src = reinterpret_cast<const float4*>(
            blend + (size_t)(tileY * TM_TC + t) * NEXP);
        float4 b0 = src[0], b1 = src[1];
        sts128(SBLEND + t * 32,
               pack_h2(b0.x, b0.x), pack_h2(b0.y, b0.y),
               pack_h2(b0.z, b0.z), pack_h2(b0.w, b0.w));
        sts128(SBLEND + t * 32 + 16,
               pack_h2(b1.x, b1.x), pack_h2(b1.y, b1.y),
               pack_h2(b1.z, b1.z), pack_h2(b1.w, b1.w));
    }
    if (wid == 0) {
        asm volatile("tcgen05.alloc.cta_group::1.sync.aligned.shared::cta.b32 [%0], %1;"
                     :: "r"(TMEMP), "r"(256u) : "memory");
        asm volatile("tcgen05.relinquish_alloc_permit.cta_group::1.sync.aligned;");
    }
    __syncthreads();
    uint32_t tmem;
    asm volatile("ld.shared.b32 %0, [%1];" : "=r"(tmem) : "r"(TMEMP));

    // idesc: dtype=F32, atype=btype=F16, N=128, M=128, K-major both
    const uint32_t IDESC = (1u << 4) | ((TN_TC / 8) << 17) | (8u << 24);

    // staging roles: 256 thr, 16B segs; row0 0..31
    const int seg = t & 7, row0 = t >> 3;
    const uint32_t so = (uint32_t)(row0 * 128 + ((seg ^ (row0 & 7)) << 4));
    const uint32_t gB0 = (uint32_t)(tileX * TN_TC + row0) * KTOT + seg * 8;
    const uint32_t gX0 = (uint32_t)(tileY * TM_TC + row0) * IN_DIM + seg * 8;
    const __half* __restrict__ pW = g_Wh;
    const __half* __restrict__ pX = g_xh;

    // B tile: 128 rows, 4 x 16B per thread (rows row0 + 32p)
    #define TC_ISSUE_B(cc)                                                     \
        do {                                                                   \
            uint32_t base = TILES + (uint32_t)((cc) % 3) * STAGE_TC + A_TILE_TC;\
            _Pragma("unroll")                                                  \
            for (int p = 0; p < 4; ++p)                                        \
                cp_async16(base + so + p * 4096,                               \
                           pW + gB0 + (cc) * KC_TC + p * 32 * KTOT);           \
            asm volatile("cp.async.commit_group;" ::: "memory");               \
        } while (0)

    // A regs prefetch: 8 rows (row0 + 32p) of x fp16
    #define TC_LOAD_AX(cc, ax)                                                 \
        do {                                                                   \
            uint32_t xoff = gX0 + (uint32_t)(((cc) & 15) << 6);                \
            _Pragma("unroll")                                                  \
            for (int p = 0; p < 8; ++p)                                        \
                (ax)[p] = *reinterpret_cast<const uint4*>(                     \
                    pX + xoff + p * 32 * IN_DIM);                              \
        } while (0)

    // scale by blend (fp16x2) + STS into stage's A slot (8 rows/thread)
    #define TC_STORE_A(cc, ax)                                                 \
        do {                                                                   \
            uint32_t abase = TILES + (uint32_t)((cc) % 3) * STAGE_TC + so;     \
            if ((cc) < 128) {                                                  \
                int e = (cc) >> 4;                                             \
                _Pragma("unroll")                                              \
                for (int p = 0; p < 8; ++p) {                                  \
                    uint32_t bl2;                                              \
                    asm volatile("ld.shared.b32 %0, [%1];" : "=r"(bl2)         \
                        : "r"(SBLEND + (uint32_t)((row0 + 32 * p) * 32 + e * 4)));\
                    const uint32_t* hv = (const uint32_t*)&(ax)[p];            \
                    sts128(abase + p * 4096,                                   \
                           hmul2(hv[0], bl2), hmul2(hv[1], bl2),               \
                           hmul2(hv[2], bl2), hmul2(hv[3], bl2));              \
                }                                                              \
            } else {                                                           \
                _Pragma("unroll")                                              \
                for (int p = 0; p < 8; ++p) {                                  \
                    uint32_t w[4] = {0u, 0u, 0u, 0u};                          \
                    if ((cc) == 128 && seg == 0) {                             \
                        _Pragma("unroll")                                      \
                        for (int q = 0; q < 4; ++q) {                          \
                            uint32_t b0, b1;                                   \
                            uint32_t rb = SBLEND +                             \
                                (uint32_t)((row0 + 32 * p) * 32 + q * 8);      \
                            asm volatile("ld.shared.b32 %0, [%1];" : "=r"(b0)  \
                                         : "r"(rb));                           \
                            asm volatile("ld.shared.b32 %0, [%1];" : "=r"(b1)  \
                                         : "r"(rb + 4));                       \
                            w[q] = (b0 & 0xFFFFu) | (b1 << 16);                \
                        }                                                      \
                    }                                                          \
                    sts128(abase + p * 4096, w[0], w[1], w[2], w[3]);          \
                }                                                              \
            }                                                                  \
        } while (0)

    // prologue: chunks 0 and 1
    {
        uint4 ax[8];
        TC_ISSUE_B(0);
        TC_ISSUE_B(1);
        TC_LOAD_AX(0, ax);
        TC_STORE_A(0, ax);
        TC_LOAD_AX(1, ax);
        TC_STORE_A(1, ax);
    }

    for (int c = 0; c < NCH_TC; ++c) {
        if (c == NCH_TC - 1)
            asm volatile("cp.async.wait_group 0;" ::: "memory");
        else
            asm volatile("cp.async.wait_group 1;" ::: "memory");
        __syncthreads();
        asm volatile("fence.proxy.async.shared::cta;" ::: "memory");

        if (wid == 0 && elect1()) {
            uint32_t base = TILES + (uint32_t)(c % 3) * STAGE_TC;
            uint64_t dA0 = smem_desc(base);                     // rows 0-127
            uint64_t dA1 = smem_desc(base + TM_TC * 64);        // rows 128-255
            uint64_t dB  = smem_desc(base + A_TILE_TC);
            #pragma unroll
            for (int s = 0; s < 4; ++s) {
                uint32_t en = (c > 0 || s > 0) ? 1u : 0u;
                tc_mma(tmem,       dA0 + s * 2, dB + s * 2, IDESC, en);
                tc_mma(tmem + 128, dA1 + s * 2, dB + s * 2, IDESC, en);
            }
            asm volatile(
                "tcgen05.commit.cta_group::1.mbarrier::arrive::one.shared::cluster.b64 [%0];"
                :: "r"((c & 1) ? MB1 : MB0) : "memory");
        }

        // prefetch A regs for c+2 (LDG latency hides under the mbar spin)
        uint4 ax[8];
        const bool more = (c + 2 < NCH_TC);
        if (more && (c + 2) < 128) TC_LOAD_AX(c + 2, ax);

        // stage (c+2)%3 == (c-1)%3: gate on chunk c-1's MMA completion
        if (c >= 1)
            mbar_wait(((c - 1) & 1) ? MB1 : MB0, (uint32_t)(((c - 1) >> 1) & 1));
        if (more) {
            TC_ISSUE_B(c + 2);
            TC_STORE_A(c + 2, ax);
        }
    }

    // final chunk (129, odd -> MB1)
    mbar_wait(MB1, (uint32_t)(((NCH_TC - 1) >> 1) & 1));
    asm volatile("tcgen05.fence::after_thread_sync;" ::: "memory");

    // Epilogue: warps 0-3 -> D0 (rows 0-127, tmem cols 0-127),
    //           warps 4-7 -> D1 (rows 128-255, tmem cols 128-255)
    {
        const int a = wid >> 2, sub = wid & 3;
        float* orow = out +
            (size_t)(tileY * TM_TC + a * 128 + sub * 32 + lid) * OUT_DIM +
            tileX * TN_TC;
        #pragma unroll
        for (int cb = 0; cb < 4; ++cb) {
            uint32_t r[32];
            TC_LDTM_X32(r, tmem + a * 128 + cb * 32);
            asm volatile("tcgen05.wait::ld.sync.aligned;" ::: "memory");
            #pragma unroll
            for (int j = 0; j < 32; j += 4) {
                float4 v = make_float4(__uint_as_float(r[j]),
                                       __uint_as_float(r[j + 1]),
                                       __uint_as_float(r[j + 2]),
                                       __uint_as_float(r[j + 3]));
                *reinterpret_cast<float4*>(orow + cb * 32 + j) = v;
            }
        }
    }
    asm volatile("tcgen05.fence::before_thread_sync;" ::: "memory");
    __syncthreads();
    if (wid == 0) {
        asm volatile("tcgen05.dealloc.cta_group::1.sync.aligned.b32 %0, %1;"
                     :: "r"(tmem), "r"(256u));
    }
#endif  // HAS_TC
}

// ===========================================================================
// Fallback (!HAS_TC only): naive correct fp32 path (compile safety; launched
// only when the host probe says the tc kernel body is empty).
// ===========================================================================
__global__ void __launch_bounds__(256)
fb_gemm_kernel(const float* __restrict__ x, const float* __restrict__ blend,
               const float* __restrict__ weight, const float* __restrict__ bias,
               float* __restrict__ out) {
#if !HAS_TC
    __shared__ float sx[IN_DIM];
    int b = blockIdx.x;
    for (int i = threadIdx.x; i < IN_DIM; i += 256)
        sx[i] = x[(size_t)b * IN_DIM + i];
    __syncthreads();
    for (int o = threadIdx.x; o < OUT_DIM; o += 256) {
        float acc = 0.0f;
        for (int e = 0; e < NEXP; ++e) {
            float w = blend[b * NEXP + e];
            const float* wr = weight + ((size_t)e * OUT_DIM + o) * IN_DIM;
            float s = 0.0f;
            for (int i = 0; i < IN_DIM; ++i) s += sx[i] * wr[i];
            acc += w * s + w * bias[(size_t)e * OUT_DIM + o];
        }
        out[(size_t)b * OUT_DIM + o] = acc;
    }
#endif
}

// ---------------------------------------------------------------------------
extern "C" void kernel_launch(void* const* d_in, const int* in_sizes, int n_in,
                              void* d_out, int out_size) {
    const float* x      = (const float*)d_in[0];
    const float* blend  = (const float*)d_in[1];
    const float* weight = (const float*)d_in[2];
    const float* bias   = (const float*)d_in[3];
    float* out = (float*)d_out;

    // Which pass did the loader pick? Host-side attribute read (graph-safe).
    cudaFuncAttributes fa{};
    cudaFuncGetAttributes(&fa, tc_gemm_kernel);
    const bool tc_live = fa.numRegs > 32;

    if (tc_live) {
        dim3 wgrid((KTOT / 8 + 255) / 256, OUT_DIM);     // (5, 1024)
        convert_w_kernel<<<wgrid, 256>>>(weight, bias);
        convert_x_kernel<<<B_TOT / 2, 256>>>(x);

        cudaFuncSetAttribute(tc_gemm_kernel,
                             cudaFuncAttributeMaxDynamicSharedMemorySize, SMEM_TC);
        dim3 tgrid(OUT_DIM / TN_TC, B_TOT / TM_TC);   // (8, 16) = 128 CTAs
        tc_gemm_kernel<<<tgrid, 256, SMEM_TC>>>(blend, out);
    } else {
        fb_gemm_kernel<<<B_TOT, 256>>>(x, blend, weight, bias, out);
    }
}

// round 15
// speedup vs baseline: 1.1160x; 1.1160x over previous
#include <cuda_runtime.h>
#include <cuda_fp16.h>
#include <stdint.h>

// ============================================================================
// ExpertLinear as ONE GEMM: C(4096x1024) = A(4096x8320) * W'(1024x8320)^T
// tcgen05 fp16 SS GEMM (fp32 accum), rel_err ~4e-4 (threshold 1e-3).
// Round 15: R13 geometry (TM=128, TN=256, grid (4,32), in-kernel A build)
// + CLUSTER(1,2,1) B MULTICAST: pairs of tileY CTAs (same tileX) need the
// same 32KB B tile per chunk; W' is pre-swizzled into chunk-contiguous
// tiles and fetched with cp.async.bulk multicast cooperative slicing
// (each CTA loads 16KB, delivers to both). B LTS traffic 545 -> 272MB;
// the GEMM flips tensor-bound (~47us floor). Per-stage empty mbarriers
// (count=2) gate cross-CTA stage reuse.
// ============================================================================

#if defined(__CUDA_ARCH_FEAT_SM103_ALL) || defined(__CUDA_ARCH_FEAT_SM100_ALL)
#define HAS_TC 1
#else
#define HAS_TC 0
#endif

#define B_TOT   4096
#define IN_DIM  1024
#define OUT_DIM 1024
#define NEXP    8
#define KTOT    8320                   // 130*64 (8192 data + 8 bias + pad)

#define KC_TC   64
#define NCH_TC  (KTOT / KC_TC)         // 130
#define TM_TC   128
#define TN_TC   256
#define A_TILE_TC (TM_TC * 128)        // 16384
#define B_TILE_TC (TN_TC * 128)        // 32768 (one pre-swizzled chunk tile)
#define STAGE_TC  (A_TILE_TC + B_TILE_TC)  // 49152
#define CTRL_TC   8192
#define SMEM_TC   (CTRL_TC + 3 * STAGE_TC) // 155648

// Global scratch (allocation-free rule: __device__ globals)
// g_Wh layout: [tileX][chunk][swizzled 256x128B tile]  (chunk-contiguous)
__device__ __align__(16) __half g_Wh[(size_t)OUT_DIM * KTOT];   // 17.0 MB
__device__ __align__(16) __half g_xh[(size_t)B_TOT * IN_DIM];   // 8.4 MB

// ---------------------------------------------------------------------------
__device__ __forceinline__ uint32_t smem_u32(const void* p) {
    uint32_t a;
    asm("{ .reg .u64 t; cvta.to.shared.u64 t, %1; cvt.u32.u64 %0, t; }"
        : "=r"(a) : "l"(p));
    return a;
}

__device__ __forceinline__ uint32_t pack_h2(float a, float b) {
    uint32_t r;
    asm("cvt.rn.f16x2.f32 %0, %1, %2;" : "=r"(r) : "f"(b), "f"(a));
    return r;
}

__device__ __forceinline__ uint32_t hmul2(uint32_t a, uint32_t b) {
    uint32_t r;
    asm("mul.f16x2 %0, %1, %2;" : "=r"(r) : "r"(a), "r"(b));
    return r;
}

__device__ __forceinline__ void mbar_wait(uint32_t mbar, uint32_t parity) {
    asm volatile(
        "{\n\t.reg .pred P;\n\t"
        "WL_%=:\n\t"
        "mbarrier.try_wait.parity.acquire.cta.shared::cta.b64 P, [%0], %1, 0x989680;\n\t"
        "@P bra.uni WD_%=;\n\t"
        "bra.uni WL_%=;\n\t"
        "WD_%=:\n\t}"
        :: "r"(mbar), "r"(parity) : "memory");
}

__device__ __forceinline__ void sts128(uint32_t addr, uint32_t a, uint32_t b,
                                       uint32_t c, uint32_t d) {
    asm volatile("st.shared.v4.b32 [%0], {%1,%2,%3,%4};"
                 :: "r"(addr), "r"(a), "r"(b), "r"(c), "r"(d) : "memory");
}

__device__ __forceinline__ uint32_t sw128d(uint32_t off) {
    return off ^ ((off >> 3) & 0x70);
}

// ---------------------------------------------------------------------------
// Kernel 1: W' -> fp16 scratch in chunk-contiguous PRE-SWIZZLED tiles.
//   tile index = tileX*NCH + c;  within tile: sw128(row*128 + col*2)
// ---------------------------------------------------------------------------
__global__ void __launch_bounds__(256)
convert_w_kernel(const float* __restrict__ weight, const float* __restrict__ bias) {
    int o = blockIdx.y;
    int kk = (blockIdx.x * 256 + threadIdx.x) * 8;
    if (kk >= KTOT) return;
    float v[8];
    if (kk < NEXP * IN_DIM) {
        int e = kk >> 10, i = kk & 1023;
        const float4* src = reinterpret_cast<const float4*>(
            weight + (size_t)e * OUT_DIM * IN_DIM + (size_t)o * IN_DIM + i);
        float4 w0 = src[0], w1 = src[1];
        v[0] = w0.x; v[1] = w0.y; v[2] = w0.z; v[3] = w0.w;
        v[4] = w1.x; v[5] = w1.y; v[6] = w1.z; v[7] = w1.w;
    } else {
        #pragma unroll
        for (int j = 0; j < 8; ++j) {
            int e = kk + j - NEXP * IN_DIM;
            v[j] = (e >= 0 && e < NEXP) ? bias[(size_t)e * OUT_DIM + o] : 0.0f;
        }
    }
    uint4 h = make_uint4(pack_h2(v[0], v[1]), pack_h2(v[2], v[3]),
                         pack_h2(v[4], v[5]), pack_h2(v[6], v[7]));
    int tX = o >> 8, row = o & 255;
    int c = kk >> 6, col = kk & 63;
    uint32_t sw = sw128d((uint32_t)(row * 128 + col * 2));
    size_t byteoff = (size_t)(tX * NCH_TC + c) * B_TILE_TC + sw;
    *reinterpret_cast<uint4*>(reinterpret_cast<char*>(g_Wh) + byteoff) = h;
}

// ---------------------------------------------------------------------------
// Kernel 2: x -> fp16 scratch. One block = 2 rows (256 thr, 8 elems each).
// ---------------------------------------------------------------------------
__global__ void __launch_bounds__(256)
convert_x_kernel(const float* __restrict__ x) {
    int b = blockIdx.x * 2 + (threadIdx.x >> 7);
    int i = (threadIdx.x & 127) * 8;
    const float4* src = reinterpret_cast<const float4*>(x + (size_t)b * IN_DIM + i);
    float4 x0 = src[0], x1 = src[1];
    uint4 h = make_uint4(pack_h2(x0.x, x0.y), pack_h2(x0.z, x0.w),
                         pack_h2(x1.x, x1.y), pack_h2(x1.z, x1.w));
    *reinterpret_cast<uint4*>(&g_xh[(size_t)b * IN_DIM + i]) = h;
}

// ===========================================================================
// tcgen05 path (compiled only when the build has an 'a'-features pass)
// ===========================================================================
#if HAS_TC

__device__ __forceinline__ bool elect1() {
    uint32_t pred;
    asm volatile(
        "{\n\t.reg .pred p;\n\t"
        "elect.sync _|p, 0xFFFFFFFF;\n\t"
        "selp.b32 %0, 1, 0, p;\n\t}"
        : "=r"(pred));
    return pred != 0;
}

__device__ __forceinline__ uint64_t smem_desc(uint32_t addr) {
    const uint64_t base = (uint64_t(2) << 61) | (uint64_t(1) << 46) |
                          (uint64_t(64) << 32) | (uint64_t(1) << 16);
    return base | ((uint64_t)(addr >> 4) & 0x3FFF);
}

__device__ __forceinline__ void tc_mma(uint32_t d, uint64_t da, uint64_t db,
                                       uint32_t idesc, uint32_t en) {
    asm volatile(
        "{\n\t.reg .pred p;\n\t"
        "setp.ne.u32 p, %5, 0;\n\t"
        "tcgen05.mma.cta_group::1.kind::f16 [%0], %1, %2, %3, {%4, %4, %4, %4}, p;\n\t}"
        :: "r"(d), "l"(da), "l"(db), "r"(idesc), "r"(0u), "r"(en)
        : "memory");
}

__device__ __forceinline__ void expect_tx(uint32_t mbar, uint32_t tx) {
    asm volatile("mbarrier.arrive.expect_tx.shared.b64 _, [%0], %1;"
                 :: "r"(mbar), "r"(tx) : "memory");
}

__device__ __forceinline__ void bulk_mc(uint32_t dst, const void* src,
                                        uint32_t bytes, uint32_t mbar,
                                        uint16_t mask) {
    asm volatile(
        "cp.async.bulk.shared::cluster.global.mbarrier::complete_tx::bytes"
        ".multicast::cluster [%0], [%1], %2, [%3], %4;"
        :: "r"(dst), "l"(src), "r"(bytes), "r"(mbar), "h"(mask) : "memory");
}

__device__ __forceinline__ void arrive_cluster(uint32_t addr, uint32_t rank) {
    asm volatile(
        "{\n\t.reg .b32 ra;\n\t"
        "mapa.shared::cluster.u32 ra, %0, %1;\n\t"
        "mbarrier.arrive.shared::cluster.b64 _, [ra];\n\t}"
        :: "r"(addr), "r"(rank) : "memory");
}

#define TC_LDTM_X32(r, ta)                                                     \
    asm volatile(                                                              \
        "tcgen05.ld.sync.aligned.32x32b.x32.b32 "                              \
        "{%0, %1, %2, %3, %4, %5, %6, %7, "                                    \
        " %8, %9, %10, %11, %12, %13, %14, %15, "                              \
        " %16, %17, %18, %19, %20, %21, %22, %23, "                            \
        " %24, %25, %26, %27, %28, %29, %30, %31}, [%32];"                     \
        : "=r"((r)[0]),  "=r"((r)[1]),  "=r"((r)[2]),  "=r"((r)[3]),           \
          "=r"((r)[4]),  "=r"((r)[5]),  "=r"((r)[6]),  "=r"((r)[7]),           \
          "=r"((r)[8]),  "=r"((r)[9]),  "=r"((r)[10]), "=r"((r)[11]),          \
          "=r"((r)[12]), "=r"((r)[13]), "=r"((r)[14]), "=r"((r)[15]),          \
          "=r"((r)[16]), "=r"((r)[17]), "=r"((r)[18]), "=r"((r)[19]),          \
          "=r"((r)[20]), "=r"((r)[21]), "=r"((r)[22]), "=r"((r)[23]),          \
          "=r"((r)[24]), "=r"((r)[25]), "=r"((r)[26]), "=r"((r)[27]),          \
          "=r"((r)[28]), "=r"((r)[29]), "=r"((r)[30]), "=r"((r)[31])           \
        : "r"(ta))

#endif  // HAS_TC

__global__ void __launch_bounds__(256, 1) __cluster_dims__(1, 2, 1)
tc_gemm_kernel(const float* __restrict__ blend, float* __restrict__ out) {
#if HAS_TC
    extern __shared__ char smem[];
    const uint32_t sb = smem_u32(smem);
    const int t = threadIdx.x;
    const int wid = t >> 5, lid = t & 31;
    const int tileX = blockIdx.x;   // 0..3  (N tiles of 256)
    const int tileY = blockIdx.y;   // 0..31 (M tiles of 128)
    uint32_t rank;
    asm("mov.u32 %0, %%cluster_ctarank;" : "=r"(rank));

    const uint32_t TMEMP = sb, MB0 = sb + 8, MB1 = sb + 16;
    const uint32_t FULLB0 = sb + 24;   // fullB[s] = FULLB0 + s*8
    const uint32_t EMPTY0 = sb + 48;   // empty[s] = EMPTY0 + s*8
    const uint32_t SBLEND = sb + 128;  // 128 rows x 8 half2(dup) = 4KB
    const uint32_t TILES = sb + CTRL_TC;

    if (t == 0) {
        asm volatile("mbarrier.init.shared.b64 [%0], 1;" :: "r"(MB0) : "memory");
        asm volatile("mbarrier.init.shared.b64 [%0], 1;" :: "r"(MB1) : "memory");
        #pragma unroll
        for (int s = 0; s < 3; ++s) {
            asm volatile("mbarrier.init.shared.b64 [%0], 1;"
                         :: "r"(FULLB0 + s * 8) : "memory");
            asm volatile("mbarrier.init.shared.b64 [%0], 2;"
                         :: "r"(EMPTY0 + s * 8) : "memory");
        }
    }
    if (t < 128) {
        const float4* src = reinterpret_cast<const float4*>(
            blend + (size_t)(tileY * TM_TC + t) * NEXP);
        float4 b0 = src[0], b1 = src[1];
        sts128(SBLEND + t * 32,
               pack_h2(b0.x, b0.x), pack_h2(b0.y, b0.y),
               pack_h2(b0.z, b0.z), pack_h2(b0.w, b0.w));
        sts128(SBLEND + t * 32 + 16,
               pack_h2(b1.x, b1.x), pack_h2(b1.y, b1.y),
               pack_h2(b1.z, b1.z), pack_h2(b1.w, b1.w));
    }
    if (wid == 0) {
        asm volatile("tcgen05.alloc.cta_group::1.sync.aligned.shared::cta.b32 [%0], %1;"
                     :: "r"(TMEMP), "r"(256u) : "memory");
        asm volatile("tcgen05.relinquish_alloc_permit.cta_group::1.sync.aligned;");
    }
    __syncthreads();
    uint32_t tmem;
    asm volatile("ld.shared.b32 %0, [%1];" : "=r"(tmem) : "r"(TMEMP));

    // all mbarriers (both CTAs) initialized before any multicast targets them
    asm volatile("barrier.cluster.arrive.aligned;" ::: "memory");
    asm volatile("barrier.cluster.wait.aligned;" ::: "memory");

    // idesc: dtype=F32, atype=btype=F16, N=256, M=128, K-major both
    const uint32_t IDESC = (1u << 4) | ((TN_TC / 8) << 17) | ((TM_TC / 16) << 24);

    // A staging roles: 256 thr, 16B segs; row0 0..31, rows row0 + 32p (p<4)
    const int seg = t & 7, row0 = t >> 3;
    const uint32_t so = (uint32_t)(row0 * 128 + ((seg ^ (row0 & 7)) << 4));
    const uint32_t gX0 = (uint32_t)(tileY * TM_TC + row0) * IN_DIM + seg * 8;
    const __half* __restrict__ pX = g_xh;
    const char* __restrict__ pWb = reinterpret_cast<const char*>(g_Wh) +
                                   (size_t)tileX * NCH_TC * B_TILE_TC;

    // B multicast: my 16KB slice of chunk cc into stage (cc%3)
    #define TC_ISSUE_B(cc)                                                     \
        do {                                                                   \
            uint32_t mb = FULLB0 + (uint32_t)((cc) % 3) * 8;                   \
            expect_tx(mb, (uint32_t)B_TILE_TC);                                \
            uint32_t dst = TILES + (uint32_t)((cc) % 3) * STAGE_TC +           \
                           A_TILE_TC + rank * (B_TILE_TC / 2);                 \
            bulk_mc(dst, pWb + (size_t)(cc) * B_TILE_TC +                      \
                             rank * (B_TILE_TC / 2),                           \
                    (uint32_t)(B_TILE_TC / 2), mb, (uint16_t)3u);              \
        } while (0)

    #define TC_LOAD_AX(cc, ax)                                                 \
        do {                                                                   \
            uint32_t xoff = gX0 + (uint32_t)(((cc) & 15) << 6);                \
            _Pragma("unroll")                                                  \
            for (int p = 0; p < 4; ++p)                                        \
                (ax)[p] = *reinterpret_cast<const uint4*>(                     \
                    pX + xoff + p * 32 * IN_DIM);                              \
        } while (0)

    #define TC_STORE_A(cc, ax)                                                 \
        do {                                                                   \
            uint32_t abase = TILES + (uint32_t)((cc) % 3) * STAGE_TC + so;     \
            if ((cc) < 128) {                                                  \
                int e = (cc) >> 4;                                             \
                _Pragma("unroll")                                              \
                for (int p = 0; p < 4; ++p) {                                  \
                    uint32_t bl2;                                              \
                    asm volatile("ld.shared.b32 %0, [%1];" : "=r"(bl2)         \
                        : "r"(SBLEND + (uint32_t)((row0 + 32 * p) * 32 + e * 4)));\
                    const uint32_t* hv = (const uint32_t*)&(ax)[p];            \
                    sts128(abase + p * 4096,                                   \
                           hmul2(hv[0], bl2), hmul2(hv[1], bl2),               \
                           hmul2(hv[2], bl2), hmul2(hv[3], bl2));              \
                }                                                              \
            } else {                                                           \
                _Pragma("unroll")                                              \
                for (int p = 0; p < 4; ++p) {                                  \
                    uint32_t w[4] = {0u, 0u, 0u, 0u};                          \
                    if ((cc) == 128 && seg == 0) {                             \
                        _Pragma("unroll")                                      \
                        for (int q = 0; q < 4; ++q) {                          \
                            uint32_t b0, b1;                                   \
                            uint32_t rb = SBLEND +                             \
                                (uint32_t)((row0 + 32 * p) * 32 + q * 8);      \
                            asm volatile("ld.shared.b32 %0, [%1];" : "=r"(b0)  \
                                         : "r"(rb));                           \
                            asm volatile("ld.shared.b32 %0, [%1];" : "=r"(b1)  \
                                         : "r"(rb + 4));                       \
                            w[q] = (b0 & 0xFFFFu) | (b1 << 16);                \
                        }                                                      \
                    }                                                          \
                    sts128(abase + p * 4096, w[0], w[1], w[2], w[3]);          \
                }                                                              \
            }                                                                  \
        } while (0)

    // prologue: fill chunks 0, 1
    {
        uint4 ax[4];
        if (t == 0) {
            TC_ISSUE_B(0);
            TC_ISSUE_B(1);
        }
        TC_LOAD_AX(0, ax);
        TC_STORE_A(0, ax);
        TC_LOAD_AX(1, ax);
        TC_STORE_A(1, ax);
    }

    for (int c = 0; c < NCH_TC; ++c) {
        // B ready (my slice + peer's slice): fill index c/3, parity (c/3)&1
        mbar_wait(FULLB0 + (uint32_t)(c % 3) * 8, (uint32_t)((c / 3) & 1));
        __syncthreads();
        asm volatile("fence.proxy.async.shared::cta;" ::: "memory");

        if (wid == 0 && elect1()) {
            uint32_t base = TILES + (uint32_t)(c % 3) * STAGE_TC;
            uint64_t da = smem_desc(base);
            uint64_t db = smem_desc(base + A_TILE_TC);
            #pragma unroll
            for (int s = 0; s < 4; ++s) {
                uint32_t en = (c > 0 || s > 0) ? 1u : 0u;
                tc_mma(tmem, da + s * 2, db + s * 2, IDESC, en);
            }
            asm volatile(
                "tcgen05.commit.cta_group::1.mbarrier::arrive::one.shared::cluster.b64 [%0];"
                :: "r"((c & 1) ? MB1 : MB0) : "memory");
        }

        uint4 ax[4];
        const bool more = (c + 2 < NCH_TC);
        if (more && (c + 2) < 128) TC_LOAD_AX(c + 2, ax);

        if (c >= 1) {
            // chunk c-1's MMAs done -> stage (c-1)%3 == (c+2)%3 is free here
            mbar_wait((c & 1) ? MB0 : MB1, (uint32_t)(((c - 1) >> 1) & 1));
            if (t == 0) {
                uint32_t emp = EMPTY0 + (uint32_t)((c - 1) % 3) * 8;
                arrive_cluster(emp, 0);
                arrive_cluster(emp, 1);
            }
        }
        if (more) {
            if (t == 0) {
                if (c >= 1)  // refills with cc>=3 wait for both CTAs' frees
                    mbar_wait(EMPTY0 + (uint32_t)((c + 2) % 3) * 8,
                              (uint32_t)(((c + 2) / 3 - 1) & 1));
                TC_ISSUE_B(c + 2);
            }
            TC_STORE_A(c + 2, ax);
        }
    }

    // final chunk (129, odd -> MB1), flip index 129/2 = 64 -> parity 0
    mbar_wait(MB1, (uint32_t)(((NCH_TC - 1) >> 1) & 1));
    asm volatile("tcgen05.fence::after_thread_sync;" ::: "memory");

    // Epilogue: warps 0-3 read 32-lane TMEM subpartitions, 256 fp32 cols
    if (wid < 4) {
        float* orow = out + (size_t)(tileY * TM_TC + wid * 32 + lid) * OUT_DIM +
                      tileX * TN_TC;
        #pragma unroll
        for (int cb = 0; cb < 8; ++cb) {
            uint32_t r[32];
            TC_LDTM_X32(r, tmem + cb * 32);
            asm volatile("tcgen05.wait::ld.sync.aligned;" ::: "memory");
            #pragma unroll
            for (int j = 0; j < 32; j += 4) {
                float4 v = make_float4(__uint_as_float(r[j]),
                                       __uint_as_float(r[j + 1]),
                                       __uint_as_float(r[j + 2]),
                                       __uint_as_float(r[j + 3]));
                *reinterpret_cast<float4*>(orow + cb * 32 + j) = v;
            }
        }
    }
    asm volatile("tcgen05.fence::before_thread_sync;" ::: "memory");
    __syncthreads();
    if (wid == 0) {
        asm volatile("tcgen05.dealloc.cta_group::1.sync.aligned.b32 %0, %1;"
                     :: "r"(tmem), "r"(256u));
    }
    // no CTA exits while peer multicasts may still target its SMEM
    asm volatile("barrier.cluster.arrive.aligned;" ::: "memory");
    asm volatile("barrier.cluster.wait.aligned;" ::: "memory");
#endif  // HAS_TC
}

// ===========================================================================
// Fallback (!HAS_TC only): naive correct fp32 path.
// ===========================================================================
__global__ void __launch_bounds__(256)
fb_gemm_kernel(const float* __restrict__ x, const float* __restrict__ blend,
               const float* __restrict__ weight, const float* __restrict__ bias,
               float* __restrict__ out) {
#if !HAS_TC
    __shared__ float sx[IN_DIM];
    int b = blockIdx.x;
    for (int i = threadIdx.x; i < IN_DIM; i += 256)
        sx[i] = x[(size_t)b * IN_DIM + i];
    __syncthreads();
    for (int o = threadIdx.x; o < OUT_DIM; o += 256) {
        float acc = 0.0f;
        for (int e = 0; e < NEXP; ++e) {
            float w = blend[b * NEXP + e];
            const float* wr = weight + ((size_t)e * OUT_DIM + o) * IN_DIM;
            float s = 0.0f;
            for (int i = 0; i < IN_DIM; ++i) s += sx[i] * wr[i];
            acc += w * s + w * bias[(size_t)e * OUT_DIM + o];
        }
        out[(size_t)b * OUT_DIM + o] = acc;
    }
#endif
}

// ---------------------------------------------------------------------------
extern "C" void kernel_launch(void* const* d_in, const int* in_sizes, int n_in,
                              void* d_out, int out_size) {
    const float* x      = (const float*)d_in[0];
    const float* blend  = (const float*)d_in[1];
    const float* weight = (const float*)d_in[2];
    const float* bias   = (const float*)d_in[3];
    float* out = (float*)d_out;

    cudaFuncAttributes fa{};
    cudaFuncGetAttributes(&fa, tc_gemm_kernel);
    const bool tc_live = fa.numRegs > 32;

    if (tc_live) {
        dim3 wgrid((KTOT / 8 + 255) / 256, OUT_DIM);     // (5, 1024)
        convert_w_kernel<<<wgrid, 256>>>(weight, bias);
        convert_x_kernel<<<B_TOT / 2, 256>>>(x);

        cudaFuncSetAttribute(tc_gemm_kernel,
                             cudaFuncAttributeMaxDynamicSharedMemorySize, SMEM_TC);
        dim3 tgrid(OUT_DIM / TN_TC, B_TOT / TM_TC);   // (4, 32) = 128 CTAs
        tc_gemm_kernel<<<tgrid, 256, SMEM_TC>>>(blend, out);
    } else {
        fb_gemm_kernel<<<B_TOT, 256>>>(x, blend, weight, bias, out);
    }
}

// round 16
// speedup vs baseline: 1.1409x; 1.0223x over previous
#include <cuda_runtime.h>
#include <cuda_fp16.h>
#include <stdint.h>

// ============================================================================
// ExpertLinear as ONE GEMM: C(4096x1024) = A(4096x8320) * W'(1024x8320)^T
// tcgen05 fp16 SS GEMM (fp32 accum), rel_err ~4e-4 (threshold 1e-3).
// Round 16: R13 (104.5us) had ~500 cyc/chunk of per-iteration fixed cost
// (sync+wait+fence+commit ladder) on top of the 512-cyc MMA floor; both
// traffic-reduction attempts (R14 geometry, R15 multicast) regressed.
// Fix the ITERATION COUNT instead: SUPER-CHUNKS of 2xKC=64 per loop pass
// (65 iterations), 2 stages x 96KB (A0,A1 + one contiguous pre-swizzled
// 64KB B block), single CTA, no cluster. W' is stored chunk-contiguous
// pre-swizzled (R15 convert) so the B refill is a perfectly linear copy.
// ============================================================================

#if defined(__CUDA_ARCH_FEAT_SM103_ALL) || defined(__CUDA_ARCH_FEAT_SM100_ALL)
#define HAS_TC 1
#else
#define HAS_TC 0
#endif

#define B_TOT   4096
#define IN_DIM  1024
#define OUT_DIM 1024
#define NEXP    8
#define KTOT    8320                   // 130*64 (8192 data + 8 bias + pad)

#define KC      64
#define NCH     (KTOT / KC)            // 130 sub-chunks
#define NSC     (NCH / 2)              // 65 super-chunks
#define TM_TC   128
#define TN_TC   256
#define SUB_A   16384                  // 128 rows x 128B
#define SUB_B   32768                  // 256 rows x 128B (pre-swizzled tile)
#define STAGE_TC (2 * SUB_A + 2 * SUB_B)   // 98304
#define CTRL_TC  8192
#define SMEM_TC  (CTRL_TC + 2 * STAGE_TC)  // 204800

// Global scratch (allocation-free rule: __device__ globals)
// g_Wh layout: [tileX][sub-chunk][pre-swizzled 256x128B tile]
__device__ __align__(16) __half g_Wh[(size_t)OUT_DIM * KTOT];   // 17.0 MB
__device__ __align__(16) __half g_xh[(size_t)B_TOT * IN_DIM];   // 8.4 MB

// ---------------------------------------------------------------------------
__device__ __forceinline__ uint32_t smem_u32(const void* p) {
    uint32_t a;
    asm("{ .reg .u64 t; cvta.to.shared.u64 t, %1; cvt.u32.u64 %0, t; }"
        : "=r"(a) : "l"(p));
    return a;
}

__device__ __forceinline__ void cp_async16(uint32_t saddr, const void* gptr) {
    asm volatile("cp.async.cg.shared.global [%0], [%1], 16;"
                 :: "r"(saddr), "l"(gptr) : "memory");
}

__device__ __forceinline__ uint32_t pack_h2(float a, float b) {
    uint32_t r;
    asm("cvt.rn.f16x2.f32 %0, %1, %2;" : "=r"(r) : "f"(b), "f"(a));
    return r;
}

__device__ __forceinline__ uint32_t hmul2(uint32_t a, uint32_t b) {
    uint32_t r;
    asm("mul.f16x2 %0, %1, %2;" : "=r"(r) : "r"(a), "r"(b));
    return r;
}

__device__ __forceinline__ void mbar_wait(uint32_t mbar, uint32_t parity) {
    asm volatile(
        "{\n\t.reg .pred P;\n\t"
        "WL_%=:\n\t"
        "mbarrier.try_wait.parity.acquire.cta.shared::cta.b64 P, [%0], %1, 0x989680;\n\t"
        "@P bra.uni WD_%=;\n\t"
        "bra.uni WL_%=;\n\t"
        "WD_%=:\n\t}"
        :: "r"(mbar), "r"(parity) : "memory");
}

__device__ __forceinline__ void sts128(uint32_t addr, uint32_t a, uint32_t b,
                                       uint32_t c, uint32_t d) {
    asm volatile("st.shared.v4.b32 [%0], {%1,%2,%3,%4};"
                 :: "r"(addr), "r"(a), "r"(b), "r"(c), "r"(d) : "memory");
}

__device__ __forceinline__ uint32_t sw128d(uint32_t off) {
    return off ^ ((off >> 3) & 0x70);
}

// ---------------------------------------------------------------------------
// Kernel 1: W' -> fp16 scratch, chunk-contiguous PRE-SWIZZLED tiles
//   tile index = tileX*NCH + c;  within tile: sw128(row*128 + col*2)
// ---------------------------------------------------------------------------
__global__ void __launch_bounds__(256)
convert_w_kernel(const float* __restrict__ weight, const float* __restrict__ bias) {
    int o = blockIdx.y;
    int kk = (blockIdx.x * 256 + threadIdx.x) * 8;
    if (kk >= KTOT) return;
    float v[8];
    if (kk < NEXP * IN_DIM) {
        int e = kk >> 10, i = kk & 1023;
        const float4* src = reinterpret_cast<const float4*>(
            weight + (size_t)e * OUT_DIM * IN_DIM + (size_t)o * IN_DIM + i);
        float4 w0 = src[0], w1 = src[1];
        v[0] = w0.x; v[1] = w0.y; v[2] = w0.z; v[3] = w0.w;
        v[4] = w1.x; v[5] = w1.y; v[6] = w1.z; v[7] = w1.w;
    } else {
        #pragma unroll
        for (int j = 0; j < 8; ++j) {
            int e = kk + j - NEXP * IN_DIM;
            v[j] = (e >= 0 && e < NEXP) ? bias[(size_t)e * OUT_DIM + o] : 0.0f;
        }
    }
    uint4 h = make_uint4(pack_h2(v[0], v[1]), pack_h2(v[2], v[3]),
                         pack_h2(v[4], v[5]), pack_h2(v[6], v[7]));
    int tX = o >> 8, row = o & 255;
    int c = kk >> 6, col = kk & 63;
    uint32_t sw = sw128d((uint32_t)(row * 128 + col * 2));
    size_t byteoff = (size_t)(tX * NCH + c) * SUB_B + sw;
    *reinterpret_cast<uint4*>(reinterpret_cast<char*>(g_Wh) + byteoff) = h;
}

// ---------------------------------------------------------------------------
// Kernel 2: x -> fp16 scratch.
// ---------------------------------------------------------------------------
__global__ void __launch_bounds__(256)
convert_x_kernel(const float* __restrict__ x) {
    int b = blockIdx.x * 2 + (threadIdx.x >> 7);
    int i = (threadIdx.x & 127) * 8;
    const float4* src = reinterpret_cast<const float4*>(x + (size_t)b * IN_DIM + i);
    float4 x0 = src[0], x1 = src[1];
    uint4 h = make_uint4(pack_h2(x0.x, x0.y), pack_h2(x0.z, x0.w),
                         pack_h2(x1.x, x1.y), pack_h2(x1.z, x1.w));
    *reinterpret_cast<uint4*>(&g_xh[(size_t)b * IN_DIM + i]) = h;
}

// ===========================================================================
// tcgen05 path
// ===========================================================================
#if HAS_TC

__device__ __forceinline__ bool elect1() {
    uint32_t pred;
    asm volatile(
        "{\n\t.reg .pred p;\n\t"
        "elect.sync _|p, 0xFFFFFFFF;\n\t"
        "selp.b32 %0, 1, 0, p;\n\t}"
        : "=r"(pred));
    return pred != 0;
}

__device__ __forceinline__ uint64_t smem_desc(uint32_t addr) {
    const uint64_t base = (uint64_t(2) << 61) | (uint64_t(1) << 46) |
                          (uint64_t(64) << 32) | (uint64_t(1) << 16);
    return base | ((uint64_t)(addr >> 4) & 0x3FFF);
}

__device__ __forceinline__ void tc_mma(uint32_t d, uint64_t da, uint64_t db,
                                       uint32_t idesc, uint32_t en) {
    asm volatile(
        "{\n\t.reg .pred p;\n\t"
        "setp.ne.u32 p, %5, 0;\n\t"
        "tcgen05.mma.cta_group::1.kind::f16 [%0], %1, %2, %3, {%4, %4, %4, %4}, p;\n\t}"
        :: "r"(d), "l"(da), "l"(db), "r"(idesc), "r"(0u), "r"(en)
        : "memory");
}

#define TC_LDTM_X32(r, ta)                                                     \
    asm volatile(                                                              \
        "tcgen05.ld.sync.aligned.32x32b.x32.b32 "                              \
        "{%0, %1, %2, %3, %4, %5, %6, %7, "                                    \
        " %8, %9, %10, %11, %12, %13, %14, %15, "                              \
        " %16, %17, %18, %19, %20, %21, %22, %23, "                            \
        " %24, %25, %26, %27, %28, %29, %30, %31}, [%32];"                     \
        : "=r"((r)[0]),  "=r"((r)[1]),  "=r"((r)[2]),  "=r"((r)[3]),           \
          "=r"((r)[4]),  "=r"((r)[5]),  "=r"((r)[6]),  "=r"((r)[7]),           \
          "=r"((r)[8]),  "=r"((r)[9]),  "=r"((r)[10]), "=r"((r)[11]),          \
          "=r"((r)[12]), "=r"((r)[13]), "=r"((r)[14]), "=r"((r)[15]),          \
          "=r"((r)[16]), "=r"((r)[17]), "=r"((r)[18]), "=r"((r)[19]),          \
          "=r"((r)[20]), "=r"((r)[21]), "=r"((r)[22]), "=r"((r)[23]),          \
          "=r"((r)[24]), "=r"((r)[25]), "=r"((r)[26]), "=r"((r)[27]),          \
          "=r"((r)[28]), "=r"((r)[29]), "=r"((r)[30]), "=r"((r)[31])           \
        : "r"(ta))

#endif  // HAS_TC

__global__ void __launch_bounds__(256, 1)
tc_gemm_kernel(const float* __restrict__ blend, float* __restrict__ out) {
#if HAS_TC
    extern __shared__ char smem[];
    const uint32_t sb = smem_u32(smem);
    const int t = threadIdx.x;
    const int wid = t >> 5, lid = t & 31;
    const int tileX = blockIdx.x;   // 0..3  (N tiles of 256)
    const int tileY = blockIdx.y;   // 0..31 (M tiles of 128)

    const uint32_t TMEMP = sb, MB0 = sb + 8, MB1 = sb + 16;
    const uint32_t SBLEND = sb + 64;          // 128 rows x 8 half2(dup) = 4KB
    const uint32_t TILES = sb + CTRL_TC;

    if (t == 0) {
        asm volatile("mbarrier.init.shared.b64 [%0], 1;" :: "r"(MB0) : "memory");
        asm volatile("mbarrier.init.shared.b64 [%0], 1;" :: "r"(MB1) : "memory");
    }
    if (t < 128) {
        const float4* src = reinterpret_cast<const float4*>(
            blend + (size_t)(tileY * TM_TC + t) * NEXP);
        float4 b0 = src[0], b1 = src[1];
        sts128(SBLEND + t * 32,
               pack_h2(b0.x, b0.x), pack_h2(b0.y, b0.y),
               pack_h2(b0.z, b0.z), pack_h2(b0.w, b0.w));
        sts128(SBLEND + t * 32 + 16,
               pack_h2(b1.x, b1.x), pack_h2(b1.y, b1.y),
               pack_h2(b1.z, b1.z), pack_h2(b1.w, b1.w));
    }
    if (wid == 0) {
        asm volatile("tcgen05.alloc.cta_group::1.sync.aligned.shared::cta.b32 [%0], %1;"
                     :: "r"(TMEMP), "r"(256u) : "memory");
        asm volatile("tcgen05.relinquish_alloc_permit.cta_group::1.sync.aligned;");
    }
    __syncthreads();
    uint32_t tmem;
    asm volatile("ld.shared.b32 %0, [%1];" : "=r"(tmem) : "r"(TMEMP));

    // idesc: dtype=F32, atype=btype=F16, N=256, M=128, K-major both
    const uint32_t IDESC = (1u << 4) | ((TN_TC / 8) << 17) | ((TM_TC / 16) << 24);

    // A staging roles: 16B segs; row0 0..31 (rows row0 + 32p, p<4)
    const int seg = t & 7, row0 = t >> 3;
    const uint32_t so = (uint32_t)(row0 * 128 + ((seg ^ (row0 & 7)) << 4));
    const uint32_t gX0 = (uint32_t)(tileY * TM_TC + row0) * IN_DIM + seg * 8;
    const __half* __restrict__ pX = g_xh;
    const char* __restrict__ pWb = reinterpret_cast<const char*>(g_Wh) +
                                   (size_t)tileX * NCH * SUB_B;

    // B refill: linear 64KB copy (2 pre-swizzled sub-tiles), 16 x 16B/thread
    #define TC_ISSUE_B(j)                                                      \
        do {                                                                   \
            uint32_t base = TILES + (uint32_t)((j) & 1) * STAGE_TC + 2 * SUB_A;\
            const char* src = pWb + (size_t)(2 * (j)) * SUB_B + t * 16;        \
            _Pragma("unroll")                                                  \
            for (int p = 0; p < 16; ++p)                                       \
                cp_async16(base + t * 16 + p * 4096, src + p * 4096);          \
            asm volatile("cp.async.commit_group;" ::: "memory");               \
        } while (0)

    // A prefetch: 4 rows of x fp16 for sub-chunk cc
    #define TC_LOAD_AX(cc, ax)                                                 \
        do {                                                                   \
            uint32_t xoff = gX0 + (uint32_t)(((cc) & 15) << 6);                \
            _Pragma("unroll")                                                  \
            for (int p = 0; p < 4; ++p)                                        \
                (ax)[p] = *reinterpret_cast<const uint4*>(                     \
                    pX + xoff + p * 32 * IN_DIM);                              \
        } while (0)

    // A store: sub-chunk cc into slot A(cc&1) of stage ((cc>>1)&1)
    #define TC_STORE_A(cc, ax)                                                 \
        do {                                                                   \
            uint32_t abase = TILES + (uint32_t)(((cc) >> 1) & 1) * STAGE_TC +  \
                             (uint32_t)((cc) & 1) * SUB_A + so;                \
            if ((cc) < 128) {                                                  \
                int e = (cc) >> 4;                                             \
                _Pragma("unroll")                                              \
                for (int p = 0; p < 4; ++p) {                                  \
                    uint32_t bl2;                                              \
                    asm volatile("ld.shared.b32 %0, [%1];" : "=r"(bl2)         \
                        : "r"(SBLEND + (uint32_t)((row0 + 32 * p) * 32 + e * 4)));\
                    const uint32_t* hv = (const uint32_t*)&(ax)[p];            \
                    sts128(abase + p * 4096,                                   \
                           hmul2(hv[0], bl2), hmul2(hv[1], bl2),               \
                           hmul2(hv[2], bl2), hmul2(hv[3], bl2));              \
                }                                                              \
            } else {                                                           \
                _Pragma("unroll")                                              \
                for (int p = 0; p < 4; ++p) {                                  \
                    uint32_t w[4] = {0u, 0u, 0u, 0u};                          \
                    if ((cc) == 128 && seg == 0) {                             \
                        _Pragma("unroll")                                      \
                        for (int q = 0; q < 4; ++q) {                          \
                            uint32_t b0, b1;                                   \
                            uint32_t rb = SBLEND +                             \
                                (uint32_t)((row0 + 32 * p) * 32 + q * 8);      \
                            asm volatile("ld.shared.b32 %0, [%1];" : "=r"(b0)  \
                                         : "r"(rb));                           \
                            asm volatile("ld.shared.b32 %0, [%1];" : "=r"(b1)  \
                                         : "r"(rb + 4));                       \
                            w[q] = (b0 & 0xFFFFu) | (b1 << 16);                \
                        }                                                      \
                    }                                                          \
                    sts128(abase + p * 4096, w[0], w[1], w[2], w[3]);          \
                }                                                              \
            }                                                                  \
        } while (0)

    // prologue: super-chunks 0 and 1 (sub-chunks 0..3)
    {
        uint4 ax[4];
        TC_ISSUE_B(0);
        TC_ISSUE_B(1);
        TC_LOAD_AX(0, ax); TC_STORE_A(0, ax);
        TC_LOAD_AX(1, ax); TC_STORE_A(1, ax);
        TC_LOAD_AX(2, ax); TC_STORE_A(2, ax);
        TC_LOAD_AX(3, ax); TC_STORE_A(3, ax);
    }

    for (int j = 0; j < NSC; ++j) {
        // B(j) landed (allow B(j+1) outstanding)
        if (j == NSC - 1)
            asm volatile("cp.async.wait_group 0;" ::: "memory");
        else
            asm volatile("cp.async.wait_group 1;" ::: "memory");
        __syncthreads();
        asm volatile("fence.proxy.async.shared::cta;" ::: "memory");

        const uint32_t base = TILES + (uint32_t)(j & 1) * STAGE_TC;
        const uint32_t mb = (j & 1) ? MB1 : MB0;

        if (wid == 0 && elect1()) {
            uint64_t dA0 = smem_desc(base);
            uint64_t dA1 = smem_desc(base + SUB_A);
            uint64_t dB0 = smem_desc(base + 2 * SUB_A);
            uint64_t dB1 = smem_desc(base + 2 * SUB_A + SUB_B);
            #pragma unroll
            for (int s = 0; s < 4; ++s)
                tc_mma(tmem, dA0 + s * 2, dB0 + s * 2, IDESC,
                       (j > 0 || s > 0) ? 1u : 0u);
            #pragma unroll
            for (int s = 0; s < 4; ++s)
                tc_mma(tmem, dA1 + s * 2, dB1 + s * 2, IDESC, 1u);
            asm volatile(
                "tcgen05.commit.cta_group::1.mbarrier::arrive::one.shared::cluster.b64 [%0];"
                :: "r"(mb) : "memory");
        }

        const bool more = (j + 2 < NSC);
        uint4 ax0[4], ax1[4];
        if (more) {
            int cc0 = 2 * (j + 2), cc1 = cc0 + 1;
            if (cc0 < 128) TC_LOAD_AX(cc0, ax0);
            if (cc1 < 128) TC_LOAD_AX(cc1, ax1);
        }

        // 2-stage: stage j&1 is reused by super-chunk j+2 -> must wait for
        // MMA(j) itself (the commit just issued). Its drain overlaps the
        // A-prefetch LDGs above. parity = (j>>1)&1 (j's commit is the
        // (j/2)-th completion on this mbar).
        mbar_wait(mb, (uint32_t)((j >> 1) & 1));

        if (more) {
            TC_ISSUE_B(j + 2);
            int cc0 = 2 * (j + 2), cc1 = cc0 + 1;
            TC_STORE_A(cc0, ax0);
            TC_STORE_A(cc1, ax1);
        } else {
            asm volatile("cp.async.commit_group;" ::: "memory");  // keep ladder
        }
    }

    asm volatile("tcgen05.fence::after_thread_sync;" ::: "memory");

    // Epilogue: warps 0-3 read their 32-lane TMEM subpartitions (256 cols)
    if (wid < 4) {
        float* orow = out + (size_t)(tileY * TM_TC + wid * 32 + lid) * OUT_DIM +
                      tileX * TN_TC;
        #pragma unroll
        for (int cb = 0; cb < 8; ++cb) {
            uint32_t r[32];
            TC_LDTM_X32(r, tmem + cb * 32);
            asm volatile("tcgen05.wait::ld.sync.aligned;" ::: "memory");
            #pragma unroll
            for (int k = 0; k < 32; k += 4) {
                float4 v = make_float4(__uint_as_float(r[k]),
                                       __uint_as_float(r[k + 1]),
                                       __uint_as_float(r[k + 2]),
                                       __uint_as_float(r[k + 3]));
                *reinterpret_cast<float4*>(orow + cb * 32 + k) = v;
            }
        }
    }
    asm volatile("tcgen05.fence::before_thread_sync;" ::: "memory");
    __syncthreads();
    if (wid == 0) {
        asm volatile("tcgen05.dealloc.cta_group::1.sync.aligned.b32 %0, %1;"
                     :: "r"(tmem), "r"(256u));
    }
#endif  // HAS_TC
}

// ===========================================================================
// Fallback (!HAS_TC only)
// ===========================================================================
__global__ void __launch_bounds__(256)
fb_gemm_kernel(const float* __restrict__ x, const float* __restrict__ blend,
               const float* __restrict__ weight, const float* __restrict__ bias,
               float* __restrict__ out) {
#if !HAS_TC
    __shared__ float sx[IN_DIM];
    int b = blockIdx.x;
    for (int i = threadIdx.x; i < IN_DIM; i += 256)
        sx[i] = x[(size_t)b * IN_DIM + i];
    __syncthreads();
    for (int o = threadIdx.x; o < OUT_DIM; o += 256) {
        float acc = 0.0f;
        for (int e = 0; e < NEXP; ++e) {
            float w = blend[b * NEXP + e];
            const float* wr = weight + ((size_t)e * OUT_DIM + o) * IN_DIM;
            float s = 0.0f;
            for (int i = 0; i < IN_DIM; ++i) s += sx[i] * wr[i];
            acc += w * s + w * bias[(size_t)e * OUT_DIM + o];
        }
        out[(size_t)b * OUT_DIM + o] = acc;
    }
#endif
}

// ---------------------------------------------------------------------------
extern "C" void kernel_launch(void* const* d_in, const int* in_sizes, int n_in,
                              void* d_out, int out_size) {
    const float* x      = (const float*)d_in[0];
    const float* blend  = (const float*)d_in[1];
    const float* weight = (const float*)d_in[2];
    const float* bias   = (const float*)d_in[3];
    float* out = (float*)d_out;

    cudaFuncAttributes fa{};
    cudaFuncGetAttributes(&fa, tc_gemm_kernel);
    const bool tc_live = fa.numRegs > 32;

    if (tc_live) {
        dim3 wgrid((KTOT / 8 + 255) / 256, OUT_DIM);     // (5, 1024)
        convert_w_kernel<<<wgrid, 256>>>(weight, bias);
        convert_x_kernel<<<B_TOT / 2, 256>>>(x);

        cudaFuncSetAttribute(tc_gemm_kernel,
                             cudaFuncAttributeMaxDynamicSharedMemorySize, SMEM_TC);
        dim3 tgrid(OUT_DIM / TN_TC, B_TOT / TM_TC);   // (4, 32) = 128 CTAs
        tc_gemm_kernel<<<tgrid, 256, SMEM_TC>>>(blend, out);
    } else {
        fb_gemm_kernel<<<B_TOT, 256>>>(x, blend, weight, bias, out);
    }
}

// round 17
// speedup vs baseline: 1.3002x; 1.1396x over previous
#include <cuda_runtime.h>
#include <cuda_fp16.h>
#include <stdint.h>

// ============================================================================
// ExpertLinear as ONE GEMM: C(4096x1024) = A(4096x8320) * W'(1024x8320)^T
// tcgen05 fp16 GEMM (fp32 accum), rel_err ~4e-4 (threshold 1e-3).
// Round 17: R13 (104.5us) is ~80% of the LTS cap (813MB L2->SM in 93us).
// Cut B traffic 2x with cta_group::2: CTA pairs (cluster (2,1,1)) compute
// M=256 x N=256; each CTA loads only its B half (16KB/chunk, was 32KB) and
// builds its own A half. Leader issues cg2 MMAs reading both CTAs' smem;
// commit multicasts to both mbars -> R13's 3-stage parity ladder unchanged.
// New per-chunk cost: one count-2 cross-CTA "full" mbar before MMA issue.
// Total LTS 813 -> 545MB. Mechanics from validated test_2cta_mma_bf16.cu.
// ============================================================================

#if defined(__CUDA_ARCH_FEAT_SM103_ALL) || defined(__CUDA_ARCH_FEAT_SM100_ALL)
#define HAS_TC 1
#else
#define HAS_TC 0
#endif

#define B_TOT   4096
#define IN_DIM  1024
#define OUT_DIM 1024
#define NEXP    8
#define KTOT    8320                   // 130*64 (8192 data + 8 bias + pad)

#define KC      64
#define NCH     (KTOT / KC)            // 130
#define TM_PAIR 256                    // M per CTA pair (128 per CTA)
#define TN      256
#define A_TILE  16384                  // 128 rows x 128B (this CTA's A half)
#define B_TILE  16384                  // 128 rows x 128B (this CTA's B half)
#define STAGE   (A_TILE + B_TILE)      // 32768
#define CTRL    8192
#define SMEM_TC (CTRL + 3 * STAGE)     // 106496

// Global scratch (allocation-free rule: __device__ globals)
__device__ __align__(16) __half g_Wh[(size_t)OUT_DIM * KTOT];   // 17.0 MB
__device__ __align__(16) __half g_xh[(size_t)B_TOT * IN_DIM];   // 8.4 MB

// ---------------------------------------------------------------------------
__device__ __forceinline__ uint32_t smem_u32(const void* p) {
    uint32_t a;
    asm("{ .reg .u64 t; cvta.to.shared.u64 t, %1; cvt.u32.u64 %0, t; }"
        : "=r"(a) : "l"(p));
    return a;
}

__device__ __forceinline__ void cp_async16(uint32_t saddr, const void* gptr) {
    asm volatile("cp.async.cg.shared.global [%0], [%1], 16;"
                 :: "r"(saddr), "l"(gptr) : "memory");
}

__device__ __forceinline__ uint32_t pack_h2(float a, float b) {
    uint32_t r;
    asm("cvt.rn.f16x2.f32 %0, %1, %2;" : "=r"(r) : "f"(b), "f"(a));
    return r;
}

__device__ __forceinline__ uint32_t hmul2(uint32_t a, uint32_t b) {
    uint32_t r;
    asm("mul.f16x2 %0, %1, %2;" : "=r"(r) : "r"(a), "r"(b));
    return r;
}

__device__ __forceinline__ void mbar_wait(uint32_t mbar, uint32_t parity) {
    asm volatile(
        "{\n\t.reg .pred P;\n\t"
        "WL_%=:\n\t"
        "mbarrier.try_wait.parity.acquire.cta.shared::cta.b64 P, [%0], %1, 0x989680;\n\t"
        "@P bra.uni WD_%=;\n\t"
        "bra.uni WL_%=;\n\t"
        "WD_%=:\n\t}"
        :: "r"(mbar), "r"(parity) : "memory");
}

__device__ __forceinline__ void mbar_wait_cluster(uint32_t mbar, uint32_t parity) {
    asm volatile(
        "{\n\t.reg .pred P;\n\t"
        "WL_%=:\n\t"
        "mbarrier.try_wait.parity.acquire.cluster.shared::cta.b64 P, [%0], %1, 0x989680;\n\t"
        "@P bra.uni WD_%=;\n\t"
        "bra.uni WL_%=;\n\t"
        "WD_%=:\n\t}"
        :: "r"(mbar), "r"(parity) : "memory");
}

__device__ __forceinline__ void sts128(uint32_t addr, uint32_t a, uint32_t b,
                                       uint32_t c, uint32_t d) {
    asm volatile("st.shared.v4.b32 [%0], {%1,%2,%3,%4};"
                 :: "r"(addr), "r"(a), "r"(b), "r"(c), "r"(d) : "memory");
}

// ---------------------------------------------------------------------------
// Kernel 1: W' (+bias columns, +zero pad) -> fp16 scratch, row-major (R13)
// ---------------------------------------------------------------------------
__global__ void __launch_bounds__(256)
convert_w_kernel(const float* __restrict__ weight, const float* __restrict__ bias) {
    int o = blockIdx.y;
    int kk = (blockIdx.x * 256 + threadIdx.x) * 8;
    if (kk >= KTOT) return;
    float v[8];
    if (kk < NEXP * IN_DIM) {
        int e = kk >> 10, i = kk & 1023;
        const float4* src = reinterpret_cast<const float4*>(
            weight + (size_t)e * OUT_DIM * IN_DIM + (size_t)o * IN_DIM + i);
        float4 w0 = src[0], w1 = src[1];
        v[0] = w0.x; v[1] = w0.y; v[2] = w0.z; v[3] = w0.w;
        v[4] = w1.x; v[5] = w1.y; v[6] = w1.z; v[7] = w1.w;
    } else {
        #pragma unroll
        for (int j = 0; j < 8; ++j) {
            int e = kk + j - NEXP * IN_DIM;
            v[j] = (e >= 0 && e < NEXP) ? bias[(size_t)e * OUT_DIM + o] : 0.0f;
        }
    }
    uint4 h = make_uint4(pack_h2(v[0], v[1]), pack_h2(v[2], v[3]),
                         pack_h2(v[4], v[5]), pack_h2(v[6], v[7]));
    *reinterpret_cast<uint4*>(&g_Wh[(size_t)o * KTOT + kk]) = h;
}

// ---------------------------------------------------------------------------
// Kernel 2: x -> fp16 scratch.
// ---------------------------------------------------------------------------
__global__ void __launch_bounds__(256)
convert_x_kernel(const float* __restrict__ x) {
    int b = blockIdx.x * 2 + (threadIdx.x >> 7);
    int i = (threadIdx.x & 127) * 8;
    const float4* src = reinterpret_cast<const float4*>(x + (size_t)b * IN_DIM + i);
    float4 x0 = src[0], x1 = src[1];
    uint4 h = make_uint4(pack_h2(x0.x, x0.y), pack_h2(x0.z, x0.w),
                         pack_h2(x1.x, x1.y), pack_h2(x1.z, x1.w));
    *reinterpret_cast<uint4*>(&g_xh[(size_t)b * IN_DIM + i]) = h;
}

// ===========================================================================
// tcgen05 path
// ===========================================================================
#if HAS_TC

__device__ __forceinline__ bool elect1() {
    uint32_t pred;
    asm volatile(
        "{\n\t.reg .pred p;\n\t"
        "elect.sync _|p, 0xFFFFFFFF;\n\t"
        "selp.b32 %0, 1, 0, p;\n\t}"
        : "=r"(pred));
    return pred != 0;
}

__device__ __forceinline__ uint64_t smem_desc(uint32_t addr) {
    const uint64_t base = (uint64_t(2) << 61) | (uint64_t(1) << 46) |
                          (uint64_t(64) << 32) | (uint64_t(1) << 16);
    return base | ((uint64_t)(addr >> 4) & 0x3FFF);
}

// cg2 kind::f16 SS MMA (fp16 in, fp32 accum)
__device__ __forceinline__ void tc_mma2(uint32_t d, uint64_t da, uint64_t db,
                                        uint32_t idesc, uint32_t en) {
    asm volatile(
        "{\n\t.reg .pred p;\n\t"
        "setp.ne.u32 p, %5, 0;\n\t"
        "tcgen05.mma.cta_group::2.kind::f16 [%0], %1, %2, %3, "
        "{%4, %4, %4, %4, %4, %4, %4, %4}, p;\n\t}"
        :: "r"(d), "l"(da), "l"(db), "r"(idesc), "r"(0u), "r"(en)
        : "memory");
}

__device__ __forceinline__ void arrive_cluster(uint32_t addr, uint32_t rank) {
    asm volatile(
        "{\n\t.reg .b32 ra;\n\t"
        "mapa.shared::cluster.u32 ra, %0, %1;\n\t"
        "mbarrier.arrive.shared::cluster.b64 _, [ra];\n\t}"
        :: "r"(addr), "r"(rank) : "memory");
}

#define TC_LDTM_X32(r, ta)                                                     \
    asm volatile(                                                              \
        "tcgen05.ld.sync.aligned.32x32b.x32.b32 "                              \
        "{%0, %1, %2, %3, %4, %5, %6, %7, "                                    \
        " %8, %9, %10, %11, %12, %13, %14, %15, "                              \
        " %16, %17, %18, %19, %20, %21, %22, %23, "                            \
        " %24, %25, %26, %27, %28, %29, %30, %31}, [%32];"                     \
        : "=r"((r)[0]),  "=r"((r)[1]),  "=r"((r)[2]),  "=r"((r)[3]),           \
          "=r"((r)[4]),  "=r"((r)[5]),  "=r"((r)[6]),  "=r"((r)[7]),           \
          "=r"((r)[8]),  "=r"((r)[9]),  "=r"((r)[10]), "=r"((r)[11]),          \
          "=r"((r)[12]), "=r"((r)[13]), "=r"((r)[14]), "=r"((r)[15]),          \
          "=r"((r)[16]), "=r"((r)[17]), "=r"((r)[18]), "=r"((r)[19]),          \
          "=r"((r)[20]), "=r"((r)[21]), "=r"((r)[22]), "=r"((r)[23]),          \
          "=r"((r)[24]), "=r"((r)[25]), "=r"((r)[26]), "=r"((r)[27]),          \
          "=r"((r)[28]), "=r"((r)[29]), "=r"((r)[30]), "=r"((r)[31])           \
        : "r"(ta))

#endif  // HAS_TC

__global__ void __launch_bounds__(256, 1) __cluster_dims__(2, 1, 1)
tc_gemm_kernel(const float* __restrict__ blend, float* __restrict__ out) {
#if HAS_TC
    extern __shared__ char smem[];
    const uint32_t sb = smem_u32(smem);
    const int t = threadIdx.x;
    const int wid = t >> 5, lid = t & 31;
    const int tileX = blockIdx.y & 3;       // N tile (256 cols)
    const int tileYp = blockIdx.y >> 2;     // M pair tile (256 rows)
    uint32_t rank;
    asm("mov.u32 %0, %%cluster_ctarank;" : "=r"(rank));

    const uint32_t TMEMP = sb, MB0 = sb + 8, MB1 = sb + 16;
    const uint32_t FULL0 = sb + 24;     // full[s] = FULL0 + s*8 (count 2)
    const uint32_t SBLEND = sb + 64;    // 128 rows x 8 half2(dup) = 4KB
    const uint32_t TILES = sb + CTRL;

    if (t == 0) {
        asm volatile("mbarrier.init.shared.b64 [%0], 1;" :: "r"(MB0) : "memory");
        asm volatile("mbarrier.init.shared.b64 [%0], 1;" :: "r"(MB1) : "memory");
        #pragma unroll
        for (int s = 0; s < 3; ++s)
            asm volatile("mbarrier.init.shared.b64 [%0], 2;"
                         :: "r"(FULL0 + s * 8) : "memory");
    }
    // blend slab for THIS CTA's 128 rows
    if (t < 128) {
        const float4* src = reinterpret_cast<const float4*>(
            blend + (size_t)(tileYp * TM_PAIR + rank * 128 + t) * NEXP);
        float4 b0 = src[0], b1 = src[1];
        sts128(SBLEND + t * 32,
               pack_h2(b0.x, b0.x), pack_h2(b0.y, b0.y),
               pack_h2(b0.z, b0.z), pack_h2(b0.w, b0.w));
        sts128(SBLEND + t * 32 + 16,
               pack_h2(b1.x, b1.x), pack_h2(b1.y, b1.y),
               pack_h2(b1.z, b1.z), pack_h2(b1.w, b1.w));
    }
    if (wid == 0) {
        asm volatile("tcgen05.alloc.cta_group::2.sync.aligned.shared::cta.b32 [%0], %1;"
                     :: "r"(TMEMP), "r"(256u) : "memory");
        asm volatile("tcgen05.relinquish_alloc_permit.cta_group::2.sync.aligned;");
    }
    __syncthreads();
    uint32_t tmem;
    asm volatile("ld.shared.b32 %0, [%1];" : "=r"(tmem) : "r"(TMEMP));

    // both CTAs' mbarriers initialized before any cross-CTA arrive/commit
    asm volatile("barrier.cluster.arrive.aligned;" ::: "memory");
    asm volatile("barrier.cluster.wait.aligned;" ::: "memory");

    // idesc: dtype=F32, atype=btype=F16, N=256, M=256 (cg2)
    const uint32_t IDESC = (1u << 4) | ((TN / 8) << 17) | ((TM_PAIR / 16) << 24);

    // staging roles: 16B segs; row0 0..31, rows row0 + 32p (p<4)
    const int seg = t & 7, row0 = t >> 3;
    const uint32_t so = (uint32_t)(row0 * 128 + ((seg ^ (row0 & 7)) << 4));
    const uint32_t gX0 =
        (uint32_t)(tileYp * TM_PAIR + rank * 128 + row0) * IN_DIM + seg * 8;
    const uint32_t gB0 =
        (uint32_t)(tileX * TN + rank * 128 + row0) * KTOT + seg * 8;
    const __half* __restrict__ pX = g_xh;
    const __half* __restrict__ pW = g_Wh;

    // B half: 128 rows, 4 x 16B per thread
    #define TC_ISSUE_B(cc)                                                     \
        do {                                                                   \
            uint32_t base = TILES + (uint32_t)((cc) % 3) * STAGE + A_TILE;     \
            _Pragma("unroll")                                                  \
            for (int p = 0; p < 4; ++p)                                        \
                cp_async16(base + so + p * 4096,                               \
                           pW + gB0 + (cc) * KC + p * 32 * KTOT);              \
            asm volatile("cp.async.commit_group;" ::: "memory");               \
        } while (0)

    #define TC_LOAD_AX(cc, ax)                                                 \
        do {                                                                   \
            uint32_t xoff = gX0 + (uint32_t)(((cc) & 15) << 6);                \
            _Pragma("unroll")                                                  \
            for (int p = 0; p < 4; ++p)                                        \
                (ax)[p] = *reinterpret_cast<const uint4*>(                     \
                    pX + xoff + p * 32 * IN_DIM);                              \
        } while (0)

    #define TC_STORE_A(cc, ax)                                                 \
        do {                                                                   \
            uint32_t abase = TILES + (uint32_t)((cc) % 3) * STAGE + so;        \
            if ((cc) < 128) {                                                  \
                int e = (cc) >> 4;                                             \
                _Pragma("unroll")                                              \
                for (int p = 0; p < 4; ++p) {                                  \
                    uint32_t bl2;                                              \
                    asm volatile("ld.shared.b32 %0, [%1];" : "=r"(bl2)         \
                        : "r"(SBLEND + (uint32_t)((row0 + 32 * p) * 32 + e * 4)));\
                    const uint32_t* hv = (const uint32_t*)&(ax)[p];            \
                    sts128(abase + p * 4096,                                   \
                           hmul2(hv[0], bl2), hmul2(hv[1], bl2),               \
                           hmul2(hv[2], bl2), hmul2(hv[3], bl2));              \
                }                                                              \
            } else {                                                           \
                _Pragma("unroll")                                              \
                for (int p = 0; p < 4; ++p) {                                  \
                    uint32_t w[4] = {0u, 0u, 0u, 0u};                          \
                    if ((cc) == 128 && seg == 0) {                             \
                        _Pragma("unroll")                                      \
                        for (int q = 0; q < 4; ++q) {                          \
                            uint32_t b0, b1;                                   \
                            uint32_t rb = SBLEND +                             \
                                (uint32_t)((row0 + 32 * p) * 32 + q * 8);      \
                            asm volatile("ld.shared.b32 %0, [%1];" : "=r"(b0)  \
                                         : "r"(rb));                           \
                            asm volatile("ld.shared.b32 %0, [%1];" : "=r"(b1)  \
                                         : "r"(rb + 4));                       \
                            w[q] = (b0 & 0xFFFFu) | (b1 << 16);                \
                        }                                                      \
                    }                                                          \
                    sts128(abase + p * 4096, w[0], w[1], w[2], w[3]);          \
                }                                                              \
            }                                                                  \
        } while (0)

    // prologue: chunks 0 and 1
    {
        uint4 ax[4];
        TC_ISSUE_B(0);
        TC_ISSUE_B(1);
        TC_LOAD_AX(0, ax); TC_STORE_A(0, ax);
        TC_LOAD_AX(1, ax); TC_STORE_A(1, ax);
    }

    for (int c = 0; c < NCH; ++c) {
        if (c == NCH - 1)
            asm volatile("cp.async.wait_group 0;" ::: "memory");
        else
            asm volatile("cp.async.wait_group 1;" ::: "memory");
        __syncthreads();
        asm volatile("fence.proxy.async.shared::cta;" ::: "memory");

        // both CTAs signal "my stage c%3 is full" to the LEADER's full mbar
        if (t == 0) arrive_cluster(FULL0 + (uint32_t)(c % 3) * 8, 0);

        if (rank == 0 && wid == 0 && elect1()) {
            // wait for both halves (count 2), fill index c/3, parity (c/3)&1
            mbar_wait_cluster(FULL0 + (uint32_t)(c % 3) * 8,
                              (uint32_t)((c / 3) & 1));
            uint32_t base = TILES + (uint32_t)(c % 3) * STAGE;
            uint64_t da = smem_desc(base);
            uint64_t db = smem_desc(base + A_TILE);
            #pragma unroll
            for (int s = 0; s < 4; ++s) {
                uint32_t en = (c > 0 || s > 0) ? 1u : 0u;
                tc_mma2(tmem, da + s * 2, db + s * 2, IDESC, en);
            }
            asm volatile(
                "tcgen05.commit.cta_group::2.mbarrier::arrive::one.shared::cluster"
                ".multicast::cluster.b64 [%0], %1;"
                :: "r"((c & 1) ? MB1 : MB0), "h"((uint16_t)3u) : "memory");
        }

        uint4 ax[4];
        const bool more = (c + 2 < NCH);
        if (more && (c + 2) < 128) TC_LOAD_AX(c + 2, ax);

        // stage (c+2)%3 == (c-1)%3: gate on chunk c-1's MMA completion
        // (multicast commit flipped BOTH CTAs' local mbars)
        if (c >= 1)
            mbar_wait((c & 1) ? MB0 : MB1, (uint32_t)(((c - 1) >> 1) & 1));
        if (more) {
            TC_ISSUE_B(c + 2);
            TC_STORE_A(c + 2, ax);
        } else {
            asm volatile("cp.async.commit_group;" ::: "memory");  // keep ladder
        }
    }

    // final chunk (129, odd -> MB1), parity ((129)>>1)&1 = 0
    mbar_wait(MB1, (uint32_t)(((NCH - 1) >> 1) & 1));
    asm volatile("tcgen05.fence::after_thread_sync;" ::: "memory");

    // Epilogue: each CTA's TMEM holds its own 128 rows x 256 cols of D
    if (wid < 4) {
        float* orow = out +
            (size_t)(tileYp * TM_PAIR + rank * 128 + wid * 32 + lid) * OUT_DIM +
            tileX * TN;
        #pragma unroll
        for (int cb = 0; cb < 8; ++cb) {
            uint32_t r[32];
            TC_LDTM_X32(r, tmem + cb * 32);
            asm volatile("tcgen05.wait::ld.sync.aligned;" ::: "memory");
            #pragma unroll
            for (int k = 0; k < 32; k += 4) {
                float4 v = make_float4(__uint_as_float(r[k]),
                                       __uint_as_float(r[k + 1]),
                                       __uint_as_float(r[k + 2]),
                                       __uint_as_float(r[k + 3]));
                *reinterpret_cast<float4*>(orow + cb * 32 + k) = v;
            }
        }
    }
    asm volatile("tcgen05.fence::before_thread_sync;" ::: "memory");
    __syncthreads();
    if (wid == 0) {
        asm volatile("tcgen05.dealloc.cta_group::2.sync.aligned.b32 %0, %1;"
                     :: "r"(tmem), "r"(256u));
    }
    // no CTA exits while the pair's MMAs/arrives may still target its SMEM
    asm volatile("barrier.cluster.arrive.aligned;" ::: "memory");
    asm volatile("barrier.cluster.wait.aligned;" ::: "memory");
#endif  // HAS_TC
}

// ===========================================================================
// Fallback (!HAS_TC only)
// ===========================================================================
__global__ void __launch_bounds__(256)
fb_gemm_kernel(const float* __restrict__ x, const float* __restrict__ blend,
               const float* __restrict__ weight, const float* __restrict__ bias,
               float* __restrict__ out) {
#if !HAS_TC
    __shared__ float sx[IN_DIM];
    int b = blockIdx.x;
    for (int i = threadIdx.x; i < IN_DIM; i += 256)
        sx[i] = x[(size_t)b * IN_DIM + i];
    __syncthreads();
    for (int o = threadIdx.x; o < OUT_DIM; o += 256) {
        float acc = 0.0f;
        for (int e = 0; e < NEXP; ++e) {
            float w = blend[b * NEXP + e];
            const float* wr = weight + ((size_t)e * OUT_DIM + o) * IN_DIM;
            float s = 0.0f;
            for (int i = 0; i < IN_DIM; ++i) s += sx[i] * wr[i];
            acc += w * s + w * bias[(size_t)e * OUT_DIM + o];
        }
        out[(size_t)b * OUT_DIM + o] = acc;
    }
#endif
}

// ---------------------------------------------------------------------------
extern "C" void kernel_launch(void* const* d_in, const int* in_sizes, int n_in,
                              void* d_out, int out_size) {
    const float* x      = (const float*)d_in[0];
    const float* blend  = (const float*)d_in[1];
    const float* weight = (const float*)d_in[2];
    const float* bias   = (const float*)d_in[3];
    float* out = (float*)d_out;

    cudaFuncAttributes fa{};
    cudaFuncGetAttributes(&fa, tc_gemm_kernel);
    const bool tc_live = fa.numRegs > 32;

    if (tc_live) {
        dim3 wgrid((KTOT / 8 + 255) / 256, OUT_DIM);     // (5, 1024)
        convert_w_kernel<<<wgrid, 256>>>(weight, bias);
        convert_x_kernel<<<B_TOT / 2, 256>>>(x);

        cudaFuncSetAttribute(tc_gemm_kernel,
                             cudaFuncAttributeMaxDynamicSharedMemorySize, SMEM_TC);
        // grid (2, 64): x = rank within M-pair (cluster dim), y = tile id
        dim3 tgrid(2, (OUT_DIM / TN) * (B_TOT / TM_PAIR));   // (2, 64)
        tc_gemm_kernel<<<tgrid, 256, SMEM_TC>>>(blend, out);
    } else {
        fb_gemm_kernel<<<B_TOT, 256>>>(x, blend, weight, bias, out);
    }
}